// round 14
// baseline (speedup 1.0000x reference)
#include <cuda_runtime.h>
#include <math.h>

#define NMmax 100000
#define NPmax 10000
#define NEmax 1000000
#define Hc  128
#define EDc 8

typedef unsigned long long ull;

__device__ float g_hmA[NMmax*Hc];
__device__ float g_hmB[NMmax*Hc];
__device__ float g_hpA[NPmax*Hc];
__device__ float g_hpB[NPmax*Hc];
__device__ float g_xs1[NMmax*Hc];
__device__ float g_xs2[NMmax*Hc];
__device__ float g_hidm[NMmax*Hc];
__device__ float g_hidp[NPmax*Hc];
__device__ float g_P[NPmax*Hc];
__device__ float g_alpham[NEmax];
__device__ float g_alphap[NEmax];
__device__ float g_ssrc1[NMmax];
__device__ float g_ssrc2[NMmax];
__device__ float g_sdstm[NMmax];
__device__ float g_sdstp[NPmax];
__device__ float g_effdstA[4*Hc];
__device__ float g_effedgeA[4*EDc];
__device__ float g_foldWm[Hc*Hc];
__device__ float g_foldBm[Hc];
__device__ float g_foldWp[Hc*Hc];
__device__ float g_foldBp[Hc];
__device__ int   g_cntm[NMmax];
__device__ int   g_curm[NMmax];
__device__ int   g_cntp[NPmax];
__device__ int   g_curp[NPmax];
__device__ int   g_offm[NMmax+1];
__device__ int   g_offp[NPmax+1];
__device__ int   g_srcm[NEmax];
__device__ int   g_srcp[NEmax];
__device__ float g_eam[NEmax*EDc];
__device__ float g_eap[NEmax*EDc];
__device__ int   g_bsumM[128];
__device__ int   g_bpreM[128];
__device__ int   g_bsumP[128];
__device__ int   g_bpreP[128];

__device__ __forceinline__ ull ffma2(ull a, ull b, ull c){
    ull d;
    asm("fma.rn.f32x2 %0, %1, %2, %3;" : "=l"(d) : "l"(a), "l"(b), "l"(c));
    return d;
}
__device__ __forceinline__ ull bcast2(float x){
    ull d;
    asm("mov.b64 %0, {%1, %1};" : "=l"(d) : "f"(x));
    return d;
}
__device__ __forceinline__ void unpack2(ull v, float& lo, float& hi){
    asm("mov.b64 {%0, %1}, %2;" : "=f"(lo), "=f"(hi) : "l"(v));
}

__global__ void zero_int(int* __restrict__ p, int n){
    int i = blockIdx.x*256 + threadIdx.x;
    if(i<n) p[i]=0;
}
__global__ void hist_kernel(const int* __restrict__ idx, int* __restrict__ cnt, int n){
    int e = blockIdx.x*256 + threadIdx.x;
    if(e<n) atomicAdd(&cnt[idx[e]], 1);
}
__global__ void scan_blk(const int* __restrict__ cnt, int* __restrict__ off,
                         int* __restrict__ bsum, int n){
    __shared__ int wsum[32];
    int base = blockIdx.x*1024;
    int t = threadIdx.x, lane=t&31, w=t>>5;
    int v = (base+t<n)?cnt[base+t]:0;
    int s=v;
    #pragma unroll
    for(int o=1;o<32;o<<=1){ int x=__shfl_up_sync(0xffffffffu,s,o); if(lane>=o) s+=x; }
    if(lane==31) wsum[w]=s;
    __syncthreads();
    if(w==0){
        int ws=wsum[lane];
        #pragma unroll
        for(int o=1;o<32;o<<=1){ int x=__shfl_up_sync(0xffffffffu,ws,o); if(lane>=o) ws+=x; }
        wsum[lane]=ws;
    }
    __syncthreads();
    int incl = s + (w>0?wsum[w-1]:0);
    if(base+t<n) off[base+t+1] = incl;
    if(t==1023) bsum[blockIdx.x] = incl;
}
__global__ void scan_top(int* __restrict__ off, const int* __restrict__ bsum,
                         int* __restrict__ bpre, int nblk){
    __shared__ int wsum[4];
    int t=threadIdx.x, lane=t&31, w=t>>5;
    int v = (t<nblk)? bsum[t]:0;
    int s=v;
    #pragma unroll
    for(int o=1;o<32;o<<=1){ int x=__shfl_up_sync(0xffffffffu,s,o); if(lane>=o) s+=x; }
    if(lane==31) wsum[w]=s;
    __syncthreads();
    int add=0;
    #pragma unroll
    for(int ww=0;ww<4;ww++) if(ww<w) add += wsum[ww];
    bpre[t] = s + add - v;
    if(t==0) off[0]=0;
}
__global__ void scan_add(int* __restrict__ off, const int* __restrict__ bpre, int n){
    int i = blockIdx.x*256 + threadIdx.x;
    if(i<n) off[i+1] += bpre[i>>10];
}
__global__ void scatter_perm(const int* __restrict__ idx, const int* __restrict__ other,
                             const float* __restrict__ eattr,
                             const int* __restrict__ off, int* __restrict__ cur,
                             int* __restrict__ srcout, float* __restrict__ eaout, int n){
    int e = blockIdx.x*256 + threadIdx.x;
    if(e<n){
        int d = idx[e];
        int p = atomicAdd(&cur[d], 1);
        int pos = off[d]+p;
        srcout[pos] = other[e];
        float4 u = __ldg((const float4*)(eattr + (size_t)e*EDc));
        float4 w = __ldg((const float4*)(eattr + (size_t)e*EDc + 4));
        *(float4*)(eaout + (size_t)pos*EDc)     = u;
        *(float4*)(eaout + (size_t)pos*EDc + 4) = w;
    }
}
__global__ void eff_all(const float* __restrict__ Wdst, const float* __restrict__ We,
                        const float* __restrict__ adst, const float* __restrict__ aedge){
    int c = blockIdx.x;
    int t = threadIdx.x;
    const float* Wd = Wdst + (size_t)c*Hc*Hc;
    const float* ad = adst + c*Hc;
    float d = 0.f;
    for(int j=0;j<Hc;j++) d = fmaf(Wd[j*Hc+t], ad[j], d);
    g_effdstA[c*Hc + t] = d;
    if(t < EDc){
        const float* W = We + (size_t)c*Hc*EDc;
        const float* ae = aedge + c*Hc;
        float e = 0.f;
        for(int j=0;j<Hc;j++) e = fmaf(W[j*EDc+t], ae[j], e);
        g_effedgeA[c*EDc + t] = e;
    }
}
// foldW[n,k] = sum_j W1[n, off+j] * Wf[j,k];  foldB[n] = sum_j W1[n,off+j]*bf[j] (+ b1[n])
__global__ void fold_kernel(const float* __restrict__ W1, const float* __restrict__ Wf,
                            const float* __restrict__ bf, const float* __restrict__ b1,
                            float* __restrict__ foldW, float* __restrict__ foldB, int off){
    int n = blockIdx.x, k = threadIdx.x;
    float acc = 0.f;
    for(int j=0;j<64;j++) acc = fmaf(W1[n*128 + off + j], Wf[j*128 + k], acc);
    foldW[n*128 + k] = acc;
    if(k==0){
        float b = b1 ? b1[n] : 0.f;
        for(int j=0;j<64;j++) b = fmaf(W1[n*128 + off + j], bf[j], b);
        foldB[n] = b;
    }
}

// ---------------- GEMM (champion) ----------------
template<int N, int K, int LDW, int ACT>
__global__ void __launch_bounds__(256) gemm_kernel(const float* __restrict__ A,
                                                   const float* __restrict__ W,
                                                   const float* __restrict__ bias,
                                                   float* __restrict__ C, int M,
                                                   const float* __restrict__ dotvec,
                                                   float* __restrict__ dotout){
    constexpr int BM = 128;
    constexpr int KC = 32;
    constexpr int TN = N/32;
    constexpr int WS = N + 4;
    constexpr int ASD = BM + 2;
    __shared__ float As[KC*ASD];
    __shared__ float Ws[KC*WS];
    int tid  = threadIdx.x;
    int warp = tid>>5, lane = tid&31;
    int r0 = warp*16;
    int c0 = lane*TN;
    int row0 = blockIdx.x*BM;
    ull acc2[8][TN];
    #pragma unroll
    for(int i=0;i<8;i++)
        #pragma unroll
        for(int j=0;j<TN;j++) acc2[i][j]=0ull;

    for(int ko=0; ko<K; ko+=KC){
        #pragma unroll
        for(int l=0; l<(BM*KC)/(256*4); l++){
            int idx = tid + l*256;
            int r = idx>>3, kq = idx&7;
            float4 v = make_float4(0,0,0,0);
            int grow = row0 + r;
            if(grow < M) v = *(const float4*)(A + (size_t)grow*K + ko + kq*4);
            As[(kq*4+0)*ASD + r] = v.x;
            As[(kq*4+1)*ASD + r] = v.y;
            As[(kq*4+2)*ASD + r] = v.z;
            As[(kq*4+3)*ASD + r] = v.w;
        }
        for(int idx=tid; idx<KC*N; idx+=256){
            int kk = idx & (KC-1), n = idx/KC;
            Ws[kk*WS + n] = W[(size_t)n*LDW + ko + kk];
        }
        __syncthreads();
        #pragma unroll 4
        for(int k=0;k<KC;k++){
            ull a2[8];
            #pragma unroll
            for(int i=0;i<8;i++) a2[i] = *(const ull*)(As + k*ASD + r0 + 2*i);
            ull wb[TN];
            if constexpr(TN==4){
                float4 w4 = *(const float4*)(Ws + k*WS + c0);
                wb[0]=bcast2(w4.x); wb[1]=bcast2(w4.y); wb[2]=bcast2(w4.z); wb[3]=bcast2(w4.w);
            } else {
                float2 w2 = *(const float2*)(Ws + k*WS + c0);
                wb[0]=bcast2(w2.x); wb[1]=bcast2(w2.y);
            }
            #pragma unroll
            for(int i=0;i<8;i++)
                #pragma unroll
                for(int j=0;j<TN;j++) acc2[i][j] = ffma2(a2[i], wb[j], acc2[i][j]);
        }
        __syncthreads();
    }
    float dv[TN];
    float dr[16];
    if(dotvec){
        #pragma unroll
        for(int j=0;j<TN;j++) dv[j] = dotvec[c0+j];
        #pragma unroll
        for(int r=0;r<16;r++) dr[r]=0.f;
    }
    #pragma unroll
    for(int i=0;i<8;i++){
        int gr0 = row0 + r0 + 2*i;
        #pragma unroll
        for(int j=0;j<TN;j++){
            float lo, hi;
            unpack2(acc2[i][j], lo, hi);
            float bv = bias ? bias[c0+j] : 0.f;
            lo += bv; hi += bv;
            if(ACT==1){ lo = fmaxf(lo,0.f); hi = fmaxf(hi,0.f); }
            if(ACT==2){ lo = lo>0.f?lo:(__expf(lo)-1.f); hi = hi>0.f?hi:(__expf(hi)-1.f); }
            if(gr0   < M) C[(size_t)gr0    *N + c0 + j] = lo;
            if(gr0+1 < M) C[(size_t)(gr0+1)*N + c0 + j] = hi;
            if(dotvec){
                dr[2*i]   = fmaf(lo, dv[j], dr[2*i]);
                dr[2*i+1] = fmaf(hi, dv[j], dr[2*i+1]);
            }
        }
    }
    if(dotvec){
        #pragma unroll
        for(int r=0;r<16;r++){
            float s = dr[r];
            #pragma unroll
            for(int o=16;o;o>>=1) s += __shfl_xor_sync(0xffffffffu, s, o);
            int grow = row0 + r0 + r;
            if(lane==0 && grow < M) dotout[grow] = s;
        }
    }
}

// ---------------- champion conv ----------------
__global__ void __launch_bounds__(256) conv_main(
    const float* __restrict__ xs, const float* __restrict__ xdst,
    const float* __restrict__ ssrc, const float* __restrict__ sdst,
    const int* __restrict__ off, const int* __restrict__ srcarr,
    const float* __restrict__ eattrp, float* __restrict__ alpha,
    const float* __restrict__ We, const float* __restrict__ effedge,
    float* __restrict__ hout, int Nd,
    const float* __restrict__ next_effdst, float* __restrict__ next_sdst)
{
    int warp = threadIdx.x>>5, lane = threadIdx.x&31;
    int d = blockIdx.x*8 + warp;
    if(d >= Nd) return;

    float ae[8];
    #pragma unroll
    for(int c=0;c<8;c++) ae[c] = __ldg(effedge + c);

    int beg = off[d];
    int deg = off[d+1] - beg;
    float sd = sdst[d];

    float amax = -3.0e38f;
    for(int i=lane; i<deg; i+=32){
        int s = __ldg(srcarr + beg+i);
        float a = __ldg(ssrc + s) + sd;
        float4 u = __ldg((const float4*)(eattrp + (size_t)(beg+i)*EDc));
        float4 w = __ldg((const float4*)(eattrp + (size_t)(beg+i)*EDc + 4));
        a = fmaf(u.x,ae[0], fmaf(u.y,ae[1], fmaf(u.z,ae[2], fmaf(u.w,ae[3], a))));
        a = fmaf(w.x,ae[4], fmaf(w.y,ae[5], fmaf(w.z,ae[6], fmaf(w.w,ae[7], a))));
        a = a>0.f ? a : 0.01f*a;
        alpha[beg+i] = a;
        amax = fmaxf(amax, a);
    }
    #pragma unroll
    for(int o=16;o;o>>=1) amax = fmaxf(amax, __shfl_xor_sync(0xffffffffu, amax, o));
    __syncwarp();

    float acc[4] = {0.f,0.f,0.f,0.f};
    float den = 0.f;
    float eaacc = 0.f;
    int q = lane>>3, c8 = lane&7;
    int i = 0;
    for(; i+4<=deg; i+=4){
        int b = beg+i;
        float ex0=__expf(alpha[b+0]-amax);
        float ex1=__expf(alpha[b+1]-amax);
        float ex2=__expf(alpha[b+2]-amax);
        float ex3=__expf(alpha[b+3]-amax);
        int s0=__ldg(srcarr+b+0), s1=__ldg(srcarr+b+1), s2=__ldg(srcarr+b+2), s3=__ldg(srcarr+b+3);
        float4 x0=__ldg((const float4*)(xs+(size_t)s0*Hc+lane*4));
        float4 x1=__ldg((const float4*)(xs+(size_t)s1*Hc+lane*4));
        float4 x2=__ldg((const float4*)(xs+(size_t)s2*Hc+lane*4));
        float4 x3=__ldg((const float4*)(xs+(size_t)s3*Hc+lane*4));
        float exq = (q==0)?ex0:(q==1)?ex1:(q==2)?ex2:ex3;
        float ev = __ldg(eattrp + (size_t)(b+q)*EDc + c8);
        eaacc = fmaf(exq, ev, eaacc);
        den += ex0+ex1+ex2+ex3;
        acc[0]=fmaf(ex0,x0.x,acc[0]); acc[1]=fmaf(ex0,x0.y,acc[1]); acc[2]=fmaf(ex0,x0.z,acc[2]); acc[3]=fmaf(ex0,x0.w,acc[3]);
        acc[0]=fmaf(ex1,x1.x,acc[0]); acc[1]=fmaf(ex1,x1.y,acc[1]); acc[2]=fmaf(ex1,x1.z,acc[2]); acc[3]=fmaf(ex1,x1.w,acc[3]);
        acc[0]=fmaf(ex2,x2.x,acc[0]); acc[1]=fmaf(ex2,x2.y,acc[1]); acc[2]=fmaf(ex2,x2.z,acc[2]); acc[3]=fmaf(ex2,x2.w,acc[3]);
        acc[0]=fmaf(ex3,x3.x,acc[0]); acc[1]=fmaf(ex3,x3.y,acc[1]); acc[2]=fmaf(ex3,x3.z,acc[2]); acc[3]=fmaf(ex3,x3.w,acc[3]);
    }
    for(; i<deg; i++){
        int b = beg+i;
        float ex = __expf(alpha[b]-amax);
        den += ex;
        int s = __ldg(srcarr+b);
        float4 xv = __ldg((const float4*)(xs+(size_t)s*Hc+lane*4));
        acc[0]=fmaf(ex,xv.x,acc[0]); acc[1]=fmaf(ex,xv.y,acc[1]); acc[2]=fmaf(ex,xv.z,acc[2]); acc[3]=fmaf(ex,xv.w,acc[3]);
        if(lane < EDc) eaacc = fmaf(ex, __ldg(eattrp + (size_t)b*EDc + lane), eaacc);
    }
    eaacc += __shfl_xor_sync(0xffffffffu, eaacc, 8);
    eaacc += __shfl_xor_sync(0xffffffffu, eaacc, 16);
    float eac[8];
    #pragma unroll
    for(int c=0;c<8;c++) eac[c] = __shfl_sync(0xffffffffu, eaacc, c);

    float inv = den>0.f ? 1.f/den : 0.f;
    float4 xd = __ldg((const float4*)(xdst + (size_t)d*Hc + lane*4));
    float xda[4] = {xd.x, xd.y, xd.z, xd.w};
    float vv[4];
    float dotp = 0.f;
    #pragma unroll
    for(int j=0;j<4;j++){
        int ch = lane*4 + j;
        float4 wa = __ldg((const float4*)(We + ch*EDc));
        float4 wb = __ldg((const float4*)(We + ch*EDc + 4));
        float ep = eac[0]*wa.x + eac[1]*wa.y + eac[2]*wa.z + eac[3]*wa.w
                 + eac[4]*wb.x + eac[5]*wb.y + eac[6]*wb.z + eac[7]*wb.w;
        float v = (acc[j] + ep)*inv + xda[j];
        v = v>0.f ? v : (__expf(v)-1.f);
        vv[j] = v;
        if(next_effdst) dotp = fmaf(v, __ldg(next_effdst + ch), dotp);
    }
    *(float4*)(hout + (size_t)d*Hc + lane*4) = make_float4(vv[0],vv[1],vv[2],vv[3]);
    if(next_effdst){
        #pragma unroll
        for(int o=16;o;o>>=1) dotp += __shfl_xor_sync(0xffffffffu, dotp, o);
        if(lane==0) next_sdst[d] = dotp;
    }
}

// 16 lanes per edge, 2 edges per warp
__global__ void __launch_bounds__(256) edge_out_kernel(
    const float* __restrict__ P, const float* __restrict__ Mt,
    const int* __restrict__ eprov, const int* __restrict__ emem,
    const float* __restrict__ W2, const float* __restrict__ b2,
    float* __restrict__ out, int E)
{
    int lane = threadIdx.x & 31;
    int l16 = lane & 15, g = lane >> 4;
    int wg = (blockIdx.x*256 + threadIdx.x) >> 5;
    int nw = (gridDim.x*256) >> 5;
    float4 w2a[8], w2b[8];
    #pragma unroll
    for(int c=0;c<8;c++){
        w2a[c] = *(const float4*)(W2 + c*128 + l16*8);
        w2b[c] = *(const float4*)(W2 + c*128 + l16*8 + 4);
    }
    float bb[8];
    #pragma unroll
    for(int c=0;c<8;c++) bb[c] = b2[c];

    for(int e0=wg*2; e0<E; e0+=nw*2){
        int e = e0 + g;
        bool valid = e < E;
        int p = valid ? __ldg(eprov+e) : 0;
        int m = valid ? __ldg(emem+e)  : 0;
        float4 pa = *(const float4*)(P  + (size_t)p*128 + l16*8);
        float4 pb = *(const float4*)(P  + (size_t)p*128 + l16*8 + 4);
        float4 ma = *(const float4*)(Mt + (size_t)m*128 + l16*8);
        float4 mb = *(const float4*)(Mt + (size_t)m*128 + l16*8 + 4);
        float4 ha, hb;
        ha.x = fmaxf(pa.x+ma.x, 0.f); ha.y = fmaxf(pa.y+ma.y, 0.f);
        ha.z = fmaxf(pa.z+ma.z, 0.f); ha.w = fmaxf(pa.w+ma.w, 0.f);
        hb.x = fmaxf(pb.x+mb.x, 0.f); hb.y = fmaxf(pb.y+mb.y, 0.f);
        hb.z = fmaxf(pb.z+mb.z, 0.f); hb.w = fmaxf(pb.w+mb.w, 0.f);
        float s[8];
        #pragma unroll
        for(int c=0;c<8;c++){
            float4 wa = w2a[c], wb = w2b[c];
            float t = fmaf(ha.x,wa.x, fmaf(ha.y,wa.y, fmaf(ha.z,wa.z, ha.w*wa.w)));
            s[c] = fmaf(hb.x,wb.x, fmaf(hb.y,wb.y, fmaf(hb.z,wb.z, fmaf(hb.w,wb.w, t))));
        }
        #pragma unroll
        for(int o=8;o;o>>=1){
            #pragma unroll
            for(int c=0;c<8;c++) s[c] += __shfl_xor_sync(0xffffffffu, s[c], o);
        }
        if(l16==0 && valid){
            float4 o1 = make_float4(s[0]+bb[0], s[1]+bb[1], s[2]+bb[2], s[3]+bb[3]);
            float4 o2 = make_float4(s[4]+bb[4], s[5]+bb[5], s[6]+bb[6], s[7]+bb[7]);
            *(float4*)(out + (size_t)e*8)     = o1;
            *(float4*)(out + (size_t)e*8 + 4) = o2;
        }
    }
}

static inline void* sym(const void* s){ void* p=nullptr; cudaGetSymbolAddress(&p, s); return p; }

extern "C" void kernel_launch(void* const* d_in, const int* in_sizes, int n_in,
                              void* d_out, int out_size) {
    const float* x_member   = (const float*)d_in[0];
    const float* x_provider = (const float*)d_in[1];
    const int*   edge_prov  = (const int*)d_in[2];
    const int*   edge_mem   = (const int*)d_in[3];
    const float* edge_attr  = (const float*)d_in[4];
    const float* proj_m_W   = (const float*)d_in[5];
    const float* proj_m_b   = (const float*)d_in[6];
    const float* proj_p_W   = (const float*)d_in[7];
    const float* proj_p_b   = (const float*)d_in[8];
    const float* conv_Wsrc  = (const float*)d_in[9];
    const float* conv_Wdst  = (const float*)d_in[10];
    const float* conv_We    = (const float*)d_in[11];
    const float* conv_asrc  = (const float*)d_in[12];
    const float* conv_adst  = (const float*)d_in[13];
    const float* conv_aedge = (const float*)d_in[14];
    const float* final_m_W  = (const float*)d_in[15];
    const float* final_m_b  = (const float*)d_in[16];
    const float* final_p_W  = (const float*)d_in[17];
    const float* final_p_b  = (const float*)d_in[18];
    const float* dec_m_W1   = (const float*)d_in[19];
    const float* dec_m_b1   = (const float*)d_in[20];
    const float* dec_m_W2   = (const float*)d_in[21];
    const float* dec_m_b2   = (const float*)d_in[22];
    const float* dec_p_W1   = (const float*)d_in[23];
    const float* dec_p_b1   = (const float*)d_in[24];
    const float* dec_p_W2   = (const float*)d_in[25];
    const float* dec_p_b2   = (const float*)d_in[26];
    const float* dec_e_W1   = (const float*)d_in[27];
    const float* dec_e_b1   = (const float*)d_in[28];
    const float* dec_e_W2   = (const float*)d_in[29];
    const float* dec_e_b2   = (const float*)d_in[30];

    const int NM = in_sizes[0] / 128;
    const int NP = in_sizes[1] / 64;
    const int E  = in_sizes[2];

    float* out = (float*)d_out;
    float* o_xhm = out;
    float* o_xhp = o_xhm + (size_t)NM*128;
    float* o_zm  = o_xhp + (size_t)NP*64;
    float* o_zp  = o_zm  + (size_t)NM*64;
    float* o_eh  = o_zp  + (size_t)NP*64;

    float* hmA = (float*)sym(g_hmA); float* hmB = (float*)sym(g_hmB);
    float* hpA = (float*)sym(g_hpA); float* hpB = (float*)sym(g_hpB);
    float* xs1 = (float*)sym(g_xs1); float* xs2 = (float*)sym(g_xs2);
    float* hidm = (float*)sym(g_hidm); float* hidp = (float*)sym(g_hidp);
    float* Ptab = (float*)sym(g_P);
    float* alm = (float*)sym(g_alpham); float* alp = (float*)sym(g_alphap);
    float* ssrc1 = (float*)sym(g_ssrc1); float* ssrc2 = (float*)sym(g_ssrc2);
    float* sdstm = (float*)sym(g_sdstm); float* sdstp = (float*)sym(g_sdstp);
    float* effdstA = (float*)sym(g_effdstA);
    float* effedgeA = (float*)sym(g_effedgeA);
    float* foldWm = (float*)sym(g_foldWm); float* foldBm = (float*)sym(g_foldBm);
    float* foldWp = (float*)sym(g_foldWp); float* foldBp = (float*)sym(g_foldBp);
    int* cntm = (int*)sym(g_cntm); int* curm = (int*)sym(g_curm);
    int* cntp = (int*)sym(g_cntp); int* curp = (int*)sym(g_curp);
    int* offm = (int*)sym(g_offm); int* offp = (int*)sym(g_offp);
    int* srcm = (int*)sym(g_srcm); int* srcp = (int*)sym(g_srcp);
    float* eam = (float*)sym(g_eam); float* eap = (float*)sym(g_eap);
    int* bsumM = (int*)sym(g_bsumM); int* bpreM = (int*)sym(g_bpreM);
    int* bsumP = (int*)sym(g_bsumP); int* bpreP = (int*)sym(g_bpreP);

    int gE = (E+255)/256;
    int nbm = (NM+1023)/1024, nbp = (NP+1023)/1024;

    static cudaStream_t s1 = nullptr, s2 = nullptr;
    static cudaEvent_t Ev[16];
    if(!s1){
        cudaStreamCreateWithFlags(&s1, cudaStreamNonBlocking);
        cudaStreamCreateWithFlags(&s2, cudaStreamNonBlocking);
        for(int i=0;i<16;i++) cudaEventCreateWithFlags(&Ev[i], cudaEventDisableTiming);
    }

    // fork
    cudaEventRecord(Ev[0], 0);
    cudaStreamWaitEvent(s1, Ev[0], 0);
    cudaStreamWaitEvent(s2, Ev[0], 0);

    eff_all<<<4,128>>>(conv_Wdst, conv_We, conv_adst, conv_aedge);
    cudaEventRecord(Ev[1], 0);
    zero_int<<<(NM+255)/256,256,0,s1>>>(cntm, NM);
    zero_int<<<(NM+255)/256,256,0,s1>>>(curm, NM);
    // s2: folded edge-table weights (weights only — run first), then CSR
    fold_kernel<<<128,128,0,s2>>>(dec_e_W1, final_m_W, final_m_b, nullptr,   foldWm, foldBm, 64);
    fold_kernel<<<128,128,0,s2>>>(dec_e_W1, final_p_W, final_p_b, dec_e_b1,  foldWp, foldBp, 0);
    cudaEventRecord(Ev[12], s2);   // folds ready
    zero_int<<<(NP+255)/256,256,0,s2>>>(cntp, NP);
    zero_int<<<(NP+255)/256,256,0,s2>>>(curp, NP);
    // flagship member projection
    gemm_kernel<128,128,128,2><<<(NM+127)/128,256>>>(x_member, proj_m_W, proj_m_b, hmA, NM,
                                                     effdstA + 0*128, sdstm);
    cudaEventRecord(Ev[2], 0);

    // s1: member CSR
    hist_kernel<<<gE,256,0,s1>>>(edge_mem, cntm, E);
    scan_blk<<<nbm,1024,0,s1>>>(cntm, offm, bsumM, NM);
    scan_top<<<1,128,0,s1>>>(offm, bsumM, bpreM, nbm);
    scan_add<<<(NM+255)/256,256,0,s1>>>(offm, bpreM, NM);
    scatter_perm<<<gE,256,0,s1>>>(edge_mem, edge_prov, edge_attr, offm, curm, srcm, eam, E);
    cudaEventRecord(Ev[3], s1);

    // s2: provider CSR + proj_p
    hist_kernel<<<gE,256,0,s2>>>(edge_prov, cntp, E);
    scan_blk<<<nbp,1024,0,s2>>>(cntp, offp, bsumP, NP);
    scan_top<<<1,128,0,s2>>>(offp, bsumP, bpreP, nbp);
    scan_add<<<(NP+255)/256,256,0,s2>>>(offp, bpreP, NP);
    scatter_perm<<<gE,256,0,s2>>>(edge_prov, edge_mem, edge_attr, offp, curp, srcp, eap, E);
    cudaStreamWaitEvent(s2, Ev[1], 0);
    gemm_kernel<128,64,64,2><<<(NP+127)/128,256,0,s2>>>(x_provider, proj_p_W, proj_p_b, hpA, NP,
                                                        effdstA + 1*128, sdstp);
    cudaEventRecord(Ev[4], s2);

    // layer 0
    cudaStreamWaitEvent(0, Ev[4], 0);
    gemm_kernel<128,128,128,0><<<(NP+127)/128,256>>>(hpA, conv_Wsrc + (size_t)0*128*128, nullptr, xs1, NP,
                                                     conv_asrc + 0*128, ssrc1);
    cudaStreamWaitEvent(0, Ev[3], 0);
    conv_main<<<(NM+7)/8,256>>>(xs1, hmA, ssrc1, sdstm, offm, srcm, eam, alm,
                                conv_We + (size_t)0*128*8, effedgeA + 0*8, hmB, NM,
                                effdstA + 2*128, sdstm);
    cudaEventRecord(Ev[5], 0);
    cudaStreamWaitEvent(s1, Ev[2], 0);
    gemm_kernel<128,128,128,0><<<(NM+127)/128,256,0,s1>>>(hmA, conv_Wsrc + (size_t)1*128*128, nullptr, xs2, NM,
                                                          conv_asrc + 1*128, ssrc2);
    cudaStreamWaitEvent(s1, Ev[4], 0);
    conv_main<<<(NP+7)/8,256,0,s1>>>(xs2, hpA, ssrc2, sdstp, offp, srcp, eap, alp,
                                     conv_We + (size_t)1*128*8, effedgeA + 1*8, hpB, NP,
                                     effdstA + 3*128, sdstp);
    cudaEventRecord(Ev[6], s1);

    // layer 1
    cudaStreamWaitEvent(0, Ev[6], 0);
    gemm_kernel<128,128,128,0><<<(NP+127)/128,256>>>(hpB, conv_Wsrc + (size_t)2*128*128, nullptr, xs1, NP,
                                                     conv_asrc + 2*128, ssrc1);
    conv_main<<<(NM+7)/8,256>>>(xs1, hmB, ssrc1, sdstm, offm, srcm, eam, alm,
                                conv_We + (size_t)2*128*8, effedgeA + 2*8, hmA, NM,
                                nullptr, nullptr);
    cudaEventRecord(Ev[7], 0);                    // hmA (final member hidden) ready
    cudaStreamWaitEvent(s1, Ev[5], 0);
    gemm_kernel<128,128,128,0><<<(NM+127)/128,256,0,s1>>>(hmB, conv_Wsrc + (size_t)3*128*128, nullptr, xs2, NM,
                                                          conv_asrc + 3*128, ssrc2);
    conv_main<<<(NP+7)/8,256,0,s1>>>(xs2, hpB, ssrc2, sdstp, offp, srcp, eap, alp,
                                     conv_We + (size_t)3*128*8, effedgeA + 3*8, hpA, NP,
                                     nullptr, nullptr);
    cudaEventRecord(Ev[13], s1);                  // hpA (final provider hidden) ready

    // s2: Mtab directly from hmA via folded weights (parallel with zm/hid/W2 on d)
    cudaStreamWaitEvent(s2, Ev[7], 0);
    gemm_kernel<128,128,128,0><<<(NM+127)/128,256,0,s2>>>(hmA, foldWm, foldBm, xs1, NM, nullptr, nullptr);
    cudaEventRecord(Ev[8], s2);                   // Mtab ready
    // s2: provider recon (zp -> hidp -> xhp); zp needs hpA from s1
    cudaStreamWaitEvent(s2, Ev[13], 0);
    gemm_kernel<64,128,128,0><<<(NP+127)/128,256,0,s2>>>(hpA, final_p_W, final_p_b, o_zp, NP, nullptr, nullptr);
    gemm_kernel<128,64,64,1><<<(NP+127)/128,256,0,s2>>>(o_zp, dec_p_W1, dec_p_b1, hidp, NP, nullptr, nullptr);
    gemm_kernel<64,128,128,0><<<(NP+127)/128,256,0,s2>>>(hidp, dec_p_W2, dec_p_b2, o_xhp, NP, nullptr, nullptr);
    cudaEventRecord(Ev[11], s2);

    // d: member decoder chain
    gemm_kernel<64,128,128,0><<<(NM+127)/128,256>>>(hmA, final_m_W, final_m_b, o_zm, NM, nullptr, nullptr);
    gemm_kernel<128,64,64,1>  <<<(NM+127)/128,256>>>(o_zm, dec_m_W1, dec_m_b1, hidm, NM, nullptr, nullptr);

    // s1: Ptab directly from hpA via folded weights, then edge_out
    cudaStreamWaitEvent(s1, Ev[12], 0);
    gemm_kernel<128,128,128,0><<<(NP+127)/128,256,0,s1>>>(hpA, foldWp, foldBp, Ptab, NP, nullptr, nullptr);
    cudaStreamWaitEvent(s1, Ev[8], 0);
    edge_out_kernel<<<2048,256,0,s1>>>(Ptab, xs1, edge_prov, edge_mem,
                                       dec_e_W2, dec_e_b2, o_eh, E);
    cudaEventRecord(Ev[9], s1);

    // d: member reconstruction (overlaps edge_out), then join all
    gemm_kernel<128,128,128,0><<<(NM+127)/128,256>>>(hidm, dec_m_W2, dec_m_b2, o_xhm, NM, nullptr, nullptr);
    cudaStreamWaitEvent(0, Ev[9], 0);
    cudaStreamWaitEvent(0, Ev[11], 0);
}

// round 15
// speedup vs baseline: 1.0350x; 1.0350x over previous
#include <cuda_runtime.h>
#include <math.h>

#define NMmax 100000
#define NPmax 10000
#define NEmax 1000000
#define Hc  128
#define EDc 8

typedef unsigned long long ull;

__device__ float g_hmA[NMmax*Hc];
__device__ float g_hmB[NMmax*Hc];
__device__ float g_hpA[NPmax*Hc];
__device__ float g_hpB[NPmax*Hc];
__device__ float g_xs1[NMmax*Hc];
__device__ float g_xs2[NMmax*Hc];
__device__ float g_hidm[NMmax*Hc];
__device__ float g_hidp[NPmax*Hc];
__device__ float g_P[NPmax*Hc];
__device__ float g_alpham[NEmax];
__device__ float g_alphap[NEmax];
__device__ float g_ssrc1[NMmax];
__device__ float g_ssrc2[NMmax];
__device__ float g_sdstm[NMmax];
__device__ float g_sdstp[NPmax];
__device__ float g_effdstA[4*Hc];
__device__ float g_effedgeA[4*EDc];
__device__ int   g_cntm[NMmax];
__device__ int   g_curm[NMmax];
__device__ int   g_cntp[NPmax];
__device__ int   g_curp[NPmax];
__device__ int   g_offm[NMmax+1];
__device__ int   g_offp[NPmax+1];
__device__ int   g_srcm[NEmax];
__device__ int   g_srcp[NEmax];
__device__ float g_eam[NEmax*EDc];
__device__ float g_eap[NEmax*EDc];
__device__ int   g_bsumM[128];
__device__ int   g_bpreM[128];
__device__ int   g_bsumP[128];
__device__ int   g_bpreP[128];

__device__ __forceinline__ ull ffma2(ull a, ull b, ull c){
    ull d;
    asm("fma.rn.f32x2 %0, %1, %2, %3;" : "=l"(d) : "l"(a), "l"(b), "l"(c));
    return d;
}
__device__ __forceinline__ ull bcast2(float x){
    ull d;
    asm("mov.b64 %0, {%1, %1};" : "=l"(d) : "f"(x));
    return d;
}
__device__ __forceinline__ void unpack2(ull v, float& lo, float& hi){
    asm("mov.b64 {%0, %1}, %2;" : "=f"(lo), "=f"(hi) : "l"(v));
}

__global__ void zero_int(int* __restrict__ p, int n){
    int i = blockIdx.x*256 + threadIdx.x;
    if(i<n) p[i]=0;
}
__global__ void hist_kernel(const int* __restrict__ idx, int* __restrict__ cnt, int n){
    int e = blockIdx.x*256 + threadIdx.x;
    if(e<n) atomicAdd(&cnt[idx[e]], 1);
}
__global__ void scan_blk(const int* __restrict__ cnt, int* __restrict__ off,
                         int* __restrict__ bsum, int n){
    __shared__ int wsum[32];
    int base = blockIdx.x*1024;
    int t = threadIdx.x, lane=t&31, w=t>>5;
    int v = (base+t<n)?cnt[base+t]:0;
    int s=v;
    #pragma unroll
    for(int o=1;o<32;o<<=1){ int x=__shfl_up_sync(0xffffffffu,s,o); if(lane>=o) s+=x; }
    if(lane==31) wsum[w]=s;
    __syncthreads();
    if(w==0){
        int ws=wsum[lane];
        #pragma unroll
        for(int o=1;o<32;o<<=1){ int x=__shfl_up_sync(0xffffffffu,ws,o); if(lane>=o) ws+=x; }
        wsum[lane]=ws;
    }
    __syncthreads();
    int incl = s + (w>0?wsum[w-1]:0);
    if(base+t<n) off[base+t+1] = incl;
    if(t==1023) bsum[blockIdx.x] = incl;
}
__global__ void scan_top(int* __restrict__ off, const int* __restrict__ bsum,
                         int* __restrict__ bpre, int nblk){
    __shared__ int wsum[4];
    int t=threadIdx.x, lane=t&31, w=t>>5;
    int v = (t<nblk)? bsum[t]:0;
    int s=v;
    #pragma unroll
    for(int o=1;o<32;o<<=1){ int x=__shfl_up_sync(0xffffffffu,s,o); if(lane>=o) s+=x; }
    if(lane==31) wsum[w]=s;
    __syncthreads();
    int add=0;
    #pragma unroll
    for(int ww=0;ww<4;ww++) if(ww<w) add += wsum[ww];
    bpre[t] = s + add - v;
    if(t==0) off[0]=0;
}
__global__ void scan_add(int* __restrict__ off, const int* __restrict__ bpre, int n){
    int i = blockIdx.x*256 + threadIdx.x;
    if(i<n) off[i+1] += bpre[i>>10];
}
__global__ void scatter_perm(const int* __restrict__ idx, const int* __restrict__ other,
                             const float* __restrict__ eattr,
                             const int* __restrict__ off, int* __restrict__ cur,
                             int* __restrict__ srcout, float* __restrict__ eaout, int n){
    int e = blockIdx.x*256 + threadIdx.x;
    if(e<n){
        int d = idx[e];
        int p = atomicAdd(&cur[d], 1);
        int pos = off[d]+p;
        srcout[pos] = other[e];
        float4 u = __ldg((const float4*)(eattr + (size_t)e*EDc));
        float4 w = __ldg((const float4*)(eattr + (size_t)e*EDc + 4));
        *(float4*)(eaout + (size_t)pos*EDc)     = u;
        *(float4*)(eaout + (size_t)pos*EDc + 4) = w;
    }
}
__global__ void eff_all(const float* __restrict__ Wdst, const float* __restrict__ We,
                        const float* __restrict__ adst, const float* __restrict__ aedge){
    int c = blockIdx.x;
    int t = threadIdx.x;
    const float* Wd = Wdst + (size_t)c*Hc*Hc;
    const float* ad = adst + c*Hc;
    float d = 0.f;
    for(int j=0;j<Hc;j++) d = fmaf(Wd[j*Hc+t], ad[j], d);
    g_effdstA[c*Hc + t] = d;
    if(t < EDc){
        const float* W = We + (size_t)c*Hc*EDc;
        const float* ae = aedge + c*Hc;
        float e = 0.f;
        for(int j=0;j<Hc;j++) e = fmaf(W[j*EDc+t], ae[j], e);
        g_effedgeA[c*EDc + t] = e;
    }
}

// ---------------- GEMM (champion: no prefetch, BM=128, 2 blocks/SM) ----------------
template<int N, int K, int LDW, int ACT>
__global__ void __launch_bounds__(256) gemm_kernel(const float* __restrict__ A,
                                                   const float* __restrict__ W,
                                                   const float* __restrict__ bias,
                                                   float* __restrict__ C, int M,
                                                   const float* __restrict__ dotvec,
                                                   float* __restrict__ dotout){
    constexpr int BM = 128;
    constexpr int KC = 32;
    constexpr int TN = N/32;
    constexpr int WS = N + 4;
    constexpr int ASD = BM + 2;
    __shared__ float As[KC*ASD];
    __shared__ float Ws[KC*WS];
    int tid  = threadIdx.x;
    int warp = tid>>5, lane = tid&31;
    int r0 = warp*16;
    int c0 = lane*TN;
    int row0 = blockIdx.x*BM;
    ull acc2[8][TN];
    #pragma unroll
    for(int i=0;i<8;i++)
        #pragma unroll
        for(int j=0;j<TN;j++) acc2[i][j]=0ull;

    for(int ko=0; ko<K; ko+=KC){
        #pragma unroll
        for(int l=0; l<(BM*KC)/(256*4); l++){
            int idx = tid + l*256;
            int r = idx>>3, kq = idx&7;
            float4 v = make_float4(0,0,0,0);
            int grow = row0 + r;
            if(grow < M) v = *(const float4*)(A + (size_t)grow*K + ko + kq*4);
            As[(kq*4+0)*ASD + r] = v.x;
            As[(kq*4+1)*ASD + r] = v.y;
            As[(kq*4+2)*ASD + r] = v.z;
            As[(kq*4+3)*ASD + r] = v.w;
        }
        for(int idx=tid; idx<KC*N; idx+=256){
            int kk = idx & (KC-1), n = idx/KC;
            Ws[kk*WS + n] = W[(size_t)n*LDW + ko + kk];
        }
        __syncthreads();
        #pragma unroll 4
        for(int k=0;k<KC;k++){
            ull a2[8];
            #pragma unroll
            for(int i=0;i<8;i++) a2[i] = *(const ull*)(As + k*ASD + r0 + 2*i);
            ull wb[TN];
            if constexpr(TN==4){
                float4 w4 = *(const float4*)(Ws + k*WS + c0);
                wb[0]=bcast2(w4.x); wb[1]=bcast2(w4.y); wb[2]=bcast2(w4.z); wb[3]=bcast2(w4.w);
            } else {
                float2 w2 = *(const float2*)(Ws + k*WS + c0);
                wb[0]=bcast2(w2.x); wb[1]=bcast2(w2.y);
            }
            #pragma unroll
            for(int i=0;i<8;i++)
                #pragma unroll
                for(int j=0;j<TN;j++) acc2[i][j] = ffma2(a2[i], wb[j], acc2[i][j]);
        }
        __syncthreads();
    }
    float dv[TN];
    float dr[16];
    if(dotvec){
        #pragma unroll
        for(int j=0;j<TN;j++) dv[j] = dotvec[c0+j];
        #pragma unroll
        for(int r=0;r<16;r++) dr[r]=0.f;
    }
    #pragma unroll
    for(int i=0;i<8;i++){
        int gr0 = row0 + r0 + 2*i;
        #pragma unroll
        for(int j=0;j<TN;j++){
            float lo, hi;
            unpack2(acc2[i][j], lo, hi);
            float bv = bias ? bias[c0+j] : 0.f;
            lo += bv; hi += bv;
            if(ACT==1){ lo = fmaxf(lo,0.f); hi = fmaxf(hi,0.f); }
            if(ACT==2){ lo = lo>0.f?lo:(__expf(lo)-1.f); hi = hi>0.f?hi:(__expf(hi)-1.f); }
            if(gr0   < M) C[(size_t)gr0    *N + c0 + j] = lo;
            if(gr0+1 < M) C[(size_t)(gr0+1)*N + c0 + j] = hi;
            if(dotvec){
                dr[2*i]   = fmaf(lo, dv[j], dr[2*i]);
                dr[2*i+1] = fmaf(hi, dv[j], dr[2*i+1]);
            }
        }
    }
    if(dotvec){
        #pragma unroll
        for(int r=0;r<16;r++){
            float s = dr[r];
            #pragma unroll
            for(int o=16;o;o>>=1) s += __shfl_xor_sync(0xffffffffu, s, o);
            int grow = row0 + r0 + r;
            if(lane==0 && grow < M) dotout[grow] = s;
        }
    }
}

// ---------------- champion conv: two-pass, logits+amax, 4-edge unroll ----------------
__global__ void __launch_bounds__(256) conv_main(
    const float* __restrict__ xs, const float* __restrict__ xdst,
    const float* __restrict__ ssrc, const float* __restrict__ sdst,
    const int* __restrict__ off, const int* __restrict__ srcarr,
    const float* __restrict__ eattrp, float* __restrict__ alpha,
    const float* __restrict__ We, const float* __restrict__ effedge,
    float* __restrict__ hout, int Nd,
    const float* __restrict__ next_effdst, float* __restrict__ next_sdst)
{
    int warp = threadIdx.x>>5, lane = threadIdx.x&31;
    int d = blockIdx.x*8 + warp;
    if(d >= Nd) return;

    float ae[8];
    #pragma unroll
    for(int c=0;c<8;c++) ae[c] = __ldg(effedge + c);

    int beg = off[d];
    int deg = off[d+1] - beg;
    float sd = sdst[d];

    float amax = -3.0e38f;
    for(int i=lane; i<deg; i+=32){
        int s = __ldg(srcarr + beg+i);
        float a = __ldg(ssrc + s) + sd;
        float4 u = __ldg((const float4*)(eattrp + (size_t)(beg+i)*EDc));
        float4 w = __ldg((const float4*)(eattrp + (size_t)(beg+i)*EDc + 4));
        a = fmaf(u.x,ae[0], fmaf(u.y,ae[1], fmaf(u.z,ae[2], fmaf(u.w,ae[3], a))));
        a = fmaf(w.x,ae[4], fmaf(w.y,ae[5], fmaf(w.z,ae[6], fmaf(w.w,ae[7], a))));
        a = a>0.f ? a : 0.01f*a;
        alpha[beg+i] = a;
        amax = fmaxf(amax, a);
    }
    #pragma unroll
    for(int o=16;o;o>>=1) amax = fmaxf(amax, __shfl_xor_sync(0xffffffffu, amax, o));
    __syncwarp();

    float acc[4] = {0.f,0.f,0.f,0.f};
    float den = 0.f;
    float eaacc = 0.f;
    int q = lane>>3, c8 = lane&7;
    int i = 0;
    for(; i+4<=deg; i+=4){
        int b = beg+i;
        float ex0=__expf(alpha[b+0]-amax);
        float ex1=__expf(alpha[b+1]-amax);
        float ex2=__expf(alpha[b+2]-amax);
        float ex3=__expf(alpha[b+3]-amax);
        int s0=__ldg(srcarr+b+0), s1=__ldg(srcarr+b+1), s2=__ldg(srcarr+b+2), s3=__ldg(srcarr+b+3);
        float4 x0=__ldg((const float4*)(xs+(size_t)s0*Hc+lane*4));
        float4 x1=__ldg((const float4*)(xs+(size_t)s1*Hc+lane*4));
        float4 x2=__ldg((const float4*)(xs+(size_t)s2*Hc+lane*4));
        float4 x3=__ldg((const float4*)(xs+(size_t)s3*Hc+lane*4));
        float exq = (q==0)?ex0:(q==1)?ex1:(q==2)?ex2:ex3;
        float ev = __ldg(eattrp + (size_t)(b+q)*EDc + c8);
        eaacc = fmaf(exq, ev, eaacc);
        den += ex0+ex1+ex2+ex3;
        acc[0]=fmaf(ex0,x0.x,acc[0]); acc[1]=fmaf(ex0,x0.y,acc[1]); acc[2]=fmaf(ex0,x0.z,acc[2]); acc[3]=fmaf(ex0,x0.w,acc[3]);
        acc[0]=fmaf(ex1,x1.x,acc[0]); acc[1]=fmaf(ex1,x1.y,acc[1]); acc[2]=fmaf(ex1,x1.z,acc[2]); acc[3]=fmaf(ex1,x1.w,acc[3]);
        acc[0]=fmaf(ex2,x2.x,acc[0]); acc[1]=fmaf(ex2,x2.y,acc[1]); acc[2]=fmaf(ex2,x2.z,acc[2]); acc[3]=fmaf(ex2,x2.w,acc[3]);
        acc[0]=fmaf(ex3,x3.x,acc[0]); acc[1]=fmaf(ex3,x3.y,acc[1]); acc[2]=fmaf(ex3,x3.z,acc[2]); acc[3]=fmaf(ex3,x3.w,acc[3]);
    }
    for(; i<deg; i++){
        int b = beg+i;
        float ex = __expf(alpha[b]-amax);
        den += ex;
        int s = __ldg(srcarr+b);
        float4 xv = __ldg((const float4*)(xs+(size_t)s*Hc+lane*4));
        acc[0]=fmaf(ex,xv.x,acc[0]); acc[1]=fmaf(ex,xv.y,acc[1]); acc[2]=fmaf(ex,xv.z,acc[2]); acc[3]=fmaf(ex,xv.w,acc[3]);
        if(lane < EDc) eaacc = fmaf(ex, __ldg(eattrp + (size_t)b*EDc + lane), eaacc);
    }
    eaacc += __shfl_xor_sync(0xffffffffu, eaacc, 8);
    eaacc += __shfl_xor_sync(0xffffffffu, eaacc, 16);
    float eac[8];
    #pragma unroll
    for(int c=0;c<8;c++) eac[c] = __shfl_sync(0xffffffffu, eaacc, c);

    float inv = den>0.f ? 1.f/den : 0.f;
    float4 xd = __ldg((const float4*)(xdst + (size_t)d*Hc + lane*4));
    float xda[4] = {xd.x, xd.y, xd.z, xd.w};
    float vv[4];
    float dotp = 0.f;
    #pragma unroll
    for(int j=0;j<4;j++){
        int ch = lane*4 + j;
        float4 wa = __ldg((const float4*)(We + ch*EDc));
        float4 wb = __ldg((const float4*)(We + ch*EDc + 4));
        float ep = eac[0]*wa.x + eac[1]*wa.y + eac[2]*wa.z + eac[3]*wa.w
                 + eac[4]*wb.x + eac[5]*wb.y + eac[6]*wb.z + eac[7]*wb.w;
        float v = (acc[j] + ep)*inv + xda[j];
        v = v>0.f ? v : (__expf(v)-1.f);
        vv[j] = v;
        if(next_effdst) dotp = fmaf(v, __ldg(next_effdst + ch), dotp);
    }
    *(float4*)(hout + (size_t)d*Hc + lane*4) = make_float4(vv[0],vv[1],vv[2],vv[3]);
    if(next_effdst){
        #pragma unroll
        for(int o=16;o;o>>=1) dotp += __shfl_xor_sync(0xffffffffu, dotp, o);
        if(lane==0) next_sdst[d] = dotp;
    }
}

// 16 lanes per edge, 2 edges per warp
__global__ void __launch_bounds__(256) edge_out_kernel(
    const float* __restrict__ P, const float* __restrict__ Mt,
    const int* __restrict__ eprov, const int* __restrict__ emem,
    const float* __restrict__ W2, const float* __restrict__ b2,
    float* __restrict__ out, int E)
{
    int lane = threadIdx.x & 31;
    int l16 = lane & 15, g = lane >> 4;
    int wg = (blockIdx.x*256 + threadIdx.x) >> 5;
    int nw = (gridDim.x*256) >> 5;
    float4 w2a[8], w2b[8];
    #pragma unroll
    for(int c=0;c<8;c++){
        w2a[c] = *(const float4*)(W2 + c*128 + l16*8);
        w2b[c] = *(const float4*)(W2 + c*128 + l16*8 + 4);
    }
    float bb[8];
    #pragma unroll
    for(int c=0;c<8;c++) bb[c] = b2[c];

    for(int e0=wg*2; e0<E; e0+=nw*2){
        int e = e0 + g;
        bool valid = e < E;
        int p = valid ? __ldg(eprov+e) : 0;
        int m = valid ? __ldg(emem+e)  : 0;
        float4 pa = *(const float4*)(P  + (size_t)p*128 + l16*8);
        float4 pb = *(const float4*)(P  + (size_t)p*128 + l16*8 + 4);
        float4 ma = *(const float4*)(Mt + (size_t)m*128 + l16*8);
        float4 mb = *(const float4*)(Mt + (size_t)m*128 + l16*8 + 4);
        float4 ha, hb;
        ha.x = fmaxf(pa.x+ma.x, 0.f); ha.y = fmaxf(pa.y+ma.y, 0.f);
        ha.z = fmaxf(pa.z+ma.z, 0.f); ha.w = fmaxf(pa.w+ma.w, 0.f);
        hb.x = fmaxf(pb.x+mb.x, 0.f); hb.y = fmaxf(pb.y+mb.y, 0.f);
        hb.z = fmaxf(pb.z+mb.z, 0.f); hb.w = fmaxf(pb.w+mb.w, 0.f);
        float s[8];
        #pragma unroll
        for(int c=0;c<8;c++){
            float4 wa = w2a[c], wb = w2b[c];
            float t = fmaf(ha.x,wa.x, fmaf(ha.y,wa.y, fmaf(ha.z,wa.z, ha.w*wa.w)));
            s[c] = fmaf(hb.x,wb.x, fmaf(hb.y,wb.y, fmaf(hb.z,wb.z, fmaf(hb.w,wb.w, t))));
        }
        #pragma unroll
        for(int o=8;o;o>>=1){
            #pragma unroll
            for(int c=0;c<8;c++) s[c] += __shfl_xor_sync(0xffffffffu, s[c], o);
        }
        if(l16==0 && valid){
            float4 o1 = make_float4(s[0]+bb[0], s[1]+bb[1], s[2]+bb[2], s[3]+bb[3]);
            float4 o2 = make_float4(s[4]+bb[4], s[5]+bb[5], s[6]+bb[6], s[7]+bb[7]);
            *(float4*)(out + (size_t)e*8)     = o1;
            *(float4*)(out + (size_t)e*8 + 4) = o2;
        }
    }
}

static inline void* sym(const void* s){ void* p=nullptr; cudaGetSymbolAddress(&p, s); return p; }

extern "C" void kernel_launch(void* const* d_in, const int* in_sizes, int n_in,
                              void* d_out, int out_size) {
    const float* x_member   = (const float*)d_in[0];
    const float* x_provider = (const float*)d_in[1];
    const int*   edge_prov  = (const int*)d_in[2];
    const int*   edge_mem   = (const int*)d_in[3];
    const float* edge_attr  = (const float*)d_in[4];
    const float* proj_m_W   = (const float*)d_in[5];
    const float* proj_m_b   = (const float*)d_in[6];
    const float* proj_p_W   = (const float*)d_in[7];
    const float* proj_p_b   = (const float*)d_in[8];
    const float* conv_Wsrc  = (const float*)d_in[9];
    const float* conv_Wdst  = (const float*)d_in[10];
    const float* conv_We    = (const float*)d_in[11];
    const float* conv_asrc  = (const float*)d_in[12];
    const float* conv_adst  = (const float*)d_in[13];
    const float* conv_aedge = (const float*)d_in[14];
    const float* final_m_W  = (const float*)d_in[15];
    const float* final_m_b  = (const float*)d_in[16];
    const float* final_p_W  = (const float*)d_in[17];
    const float* final_p_b  = (const float*)d_in[18];
    const float* dec_m_W1   = (const float*)d_in[19];
    const float* dec_m_b1   = (const float*)d_in[20];
    const float* dec_m_W2   = (const float*)d_in[21];
    const float* dec_m_b2   = (const float*)d_in[22];
    const float* dec_p_W1   = (const float*)d_in[23];
    const float* dec_p_b1   = (const float*)d_in[24];
    const float* dec_p_W2   = (const float*)d_in[25];
    const float* dec_p_b2   = (const float*)d_in[26];
    const float* dec_e_W1   = (const float*)d_in[27];
    const float* dec_e_b1   = (const float*)d_in[28];
    const float* dec_e_W2   = (const float*)d_in[29];
    const float* dec_e_b2   = (const float*)d_in[30];

    const int NM = in_sizes[0] / 128;
    const int NP = in_sizes[1] / 64;
    const int E  = in_sizes[2];

    float* out = (float*)d_out;
    float* o_xhm = out;
    float* o_xhp = o_xhm + (size_t)NM*128;
    float* o_zm  = o_xhp + (size_t)NP*64;
    float* o_zp  = o_zm  + (size_t)NM*64;
    float* o_eh  = o_zp  + (size_t)NP*64;

    float* hmA = (float*)sym(g_hmA); float* hmB = (float*)sym(g_hmB);
    float* hpA = (float*)sym(g_hpA); float* hpB = (float*)sym(g_hpB);
    float* xs1 = (float*)sym(g_xs1); float* xs2 = (float*)sym(g_xs2);
    float* hidm = (float*)sym(g_hidm); float* hidp = (float*)sym(g_hidp);
    float* Ptab = (float*)sym(g_P);
    float* alm = (float*)sym(g_alpham); float* alp = (float*)sym(g_alphap);
    float* ssrc1 = (float*)sym(g_ssrc1); float* ssrc2 = (float*)sym(g_ssrc2);
    float* sdstm = (float*)sym(g_sdstm); float* sdstp = (float*)sym(g_sdstp);
    float* effdstA = (float*)sym(g_effdstA);
    float* effedgeA = (float*)sym(g_effedgeA);
    int* cntm = (int*)sym(g_cntm); int* curm = (int*)sym(g_curm);
    int* cntp = (int*)sym(g_cntp); int* curp = (int*)sym(g_curp);
    int* offm = (int*)sym(g_offm); int* offp = (int*)sym(g_offp);
    int* srcm = (int*)sym(g_srcm); int* srcp = (int*)sym(g_srcp);
    float* eam = (float*)sym(g_eam); float* eap = (float*)sym(g_eap);
    int* bsumM = (int*)sym(g_bsumM); int* bpreM = (int*)sym(g_bpreM);
    int* bsumP = (int*)sym(g_bsumP); int* bpreP = (int*)sym(g_bpreP);

    int gE = (E+255)/256;
    int nbm = (NM+1023)/1024, nbp = (NP+1023)/1024;

    static cudaStream_t s1 = nullptr, s2 = nullptr;
    static cudaEvent_t Ev[12];
    if(!s1){
        cudaStreamCreateWithFlags(&s1, cudaStreamNonBlocking);
        cudaStreamCreateWithFlags(&s2, cudaStreamNonBlocking);
        for(int i=0;i<12;i++) cudaEventCreateWithFlags(&Ev[i], cudaEventDisableTiming);
    }

    // fork
    cudaEventRecord(Ev[0], 0);
    cudaStreamWaitEvent(s1, Ev[0], 0);
    cudaStreamWaitEvent(s2, Ev[0], 0);

    eff_all<<<4,128>>>(conv_Wdst, conv_We, conv_adst, conv_aedge);
    cudaEventRecord(Ev[1], 0);
    zero_int<<<(NM+255)/256,256,0,s1>>>(cntm, NM);
    zero_int<<<(NM+255)/256,256,0,s1>>>(curm, NM);
    zero_int<<<(NP+255)/256,256,0,s2>>>(cntp, NP);
    zero_int<<<(NP+255)/256,256,0,s2>>>(curp, NP);
    // flagship member projection
    gemm_kernel<128,128,128,2><<<(NM+127)/128,256>>>(x_member, proj_m_W, proj_m_b, hmA, NM,
                                                     effdstA + 0*128, sdstm);
    cudaEventRecord(Ev[2], 0);

    // s1: member CSR
    hist_kernel<<<gE,256,0,s1>>>(edge_mem, cntm, E);
    scan_blk<<<nbm,1024,0,s1>>>(cntm, offm, bsumM, NM);
    scan_top<<<1,128,0,s1>>>(offm, bsumM, bpreM, nbm);
    scan_add<<<(NM+255)/256,256,0,s1>>>(offm, bpreM, NM);
    scatter_perm<<<gE,256,0,s1>>>(edge_mem, edge_prov, edge_attr, offm, curm, srcm, eam, E);
    cudaEventRecord(Ev[3], s1);

    // s2: provider CSR + proj_p
    hist_kernel<<<gE,256,0,s2>>>(edge_prov, cntp, E);
    scan_blk<<<nbp,1024,0,s2>>>(cntp, offp, bsumP, NP);
    scan_top<<<1,128,0,s2>>>(offp, bsumP, bpreP, nbp);
    scan_add<<<(NP+255)/256,256,0,s2>>>(offp, bpreP, NP);
    scatter_perm<<<gE,256,0,s2>>>(edge_prov, edge_mem, edge_attr, offp, curp, srcp, eap, E);
    cudaStreamWaitEvent(s2, Ev[1], 0);
    gemm_kernel<128,64,64,2><<<(NP+127)/128,256,0,s2>>>(x_provider, proj_p_W, proj_p_b, hpA, NP,
                                                        effdstA + 1*128, sdstp);
    cudaEventRecord(Ev[4], s2);

    // layer 0
    cudaStreamWaitEvent(0, Ev[4], 0);
    gemm_kernel<128,128,128,0><<<(NP+127)/128,256>>>(hpA, conv_Wsrc + (size_t)0*128*128, nullptr, xs1, NP,
                                                     conv_asrc + 0*128, ssrc1);
    cudaStreamWaitEvent(0, Ev[3], 0);
    conv_main<<<(NM+7)/8,256>>>(xs1, hmA, ssrc1, sdstm, offm, srcm, eam, alm,
                                conv_We + (size_t)0*128*8, effedgeA + 0*8, hmB, NM,
                                effdstA + 2*128, sdstm);
    cudaEventRecord(Ev[5], 0);
    cudaStreamWaitEvent(s1, Ev[2], 0);
    gemm_kernel<128,128,128,0><<<(NM+127)/128,256,0,s1>>>(hmA, conv_Wsrc + (size_t)1*128*128, nullptr, xs2, NM,
                                                          conv_asrc + 1*128, ssrc2);
    cudaStreamWaitEvent(s1, Ev[4], 0);
    conv_main<<<(NP+7)/8,256,0,s1>>>(xs2, hpA, ssrc2, sdstp, offp, srcp, eap, alp,
                                     conv_We + (size_t)1*128*8, effedgeA + 1*8, hpB, NP,
                                     effdstA + 3*128, sdstp);
    cudaEventRecord(Ev[6], s1);

    // layer 1
    cudaStreamWaitEvent(0, Ev[6], 0);
    gemm_kernel<128,128,128,0><<<(NP+127)/128,256>>>(hpB, conv_Wsrc + (size_t)2*128*128, nullptr, xs1, NP,
                                                     conv_asrc + 2*128, ssrc1);
    conv_main<<<(NM+7)/8,256>>>(xs1, hmB, ssrc1, sdstm, offm, srcm, eam, alm,
                                conv_We + (size_t)2*128*8, effedgeA + 2*8, hmA, NM,
                                nullptr, nullptr);
    cudaStreamWaitEvent(s1, Ev[5], 0);
    gemm_kernel<128,128,128,0><<<(NM+127)/128,256,0,s1>>>(hmB, conv_Wsrc + (size_t)3*128*128, nullptr, xs2, NM,
                                                          conv_asrc + 3*128, ssrc2);
    conv_main<<<(NP+7)/8,256,0,s1>>>(xs2, hpB, ssrc2, sdstp, offp, srcp, eap, alp,
                                     conv_We + (size_t)3*128*8, effedgeA + 3*8, hpA, NP,
                                     nullptr, nullptr);

    // member decoder head on d: zm, fork Mtab to s2
    gemm_kernel<64,128,128,0><<<(NM+127)/128,256>>>(hmA, final_m_W, final_m_b, o_zm, NM, nullptr, nullptr);
    cudaEventRecord(Ev[7], 0);                    // zm ready
    cudaStreamWaitEvent(s2, Ev[7], 0);
    gemm_kernel<128,64,128,0><<<(NM+127)/128,256,0,s2>>>(o_zm, dec_e_W1 + 64, nullptr, xs1, NM, nullptr, nullptr);
    cudaEventRecord(Ev[8], s2);                   // Mtab ready
    gemm_kernel<128,64,64,1>  <<<(NM+127)/128,256>>>(o_zm, dec_m_W1, dec_m_b1, hidm, NM, nullptr, nullptr);

    // s1: zp -> Ptab -> edge_out (hidp/xhp moved to s2)
    gemm_kernel<64,128,128,0><<<(NP+127)/128,256,0,s1>>>(hpA, final_p_W, final_p_b, o_zp, NP, nullptr, nullptr);
    cudaEventRecord(Ev[10], s1);                  // zp ready
    gemm_kernel<128,64,128,0><<<(NP+127)/128,256,0,s1>>>(o_zp, dec_e_W1, dec_e_b1, Ptab, NP, nullptr, nullptr);
    cudaStreamWaitEvent(s1, Ev[8], 0);
    edge_out_kernel<<<2048,256,0,s1>>>(Ptab, xs1, edge_prov, edge_mem,
                                       dec_e_W2, dec_e_b2, o_eh, E);
    cudaEventRecord(Ev[9], s1);

    // s2: provider reconstruction after Mtab (needs zp)
    cudaStreamWaitEvent(s2, Ev[10], 0);
    gemm_kernel<128,64,64,1><<<(NP+127)/128,256,0,s2>>>(o_zp, dec_p_W1, dec_p_b1, hidp, NP, nullptr, nullptr);
    gemm_kernel<64,128,128,0><<<(NP+127)/128,256,0,s2>>>(hidp, dec_p_W2, dec_p_b2, o_xhp, NP, nullptr, nullptr);
    cudaEventRecord(Ev[11], s2);

    // d: member reconstruction (overlaps edge_out), then join all
    gemm_kernel<128,128,128,0><<<(NM+127)/128,256>>>(hidm, dec_m_W2, dec_m_b2, o_xhm, NM, nullptr, nullptr);
    cudaStreamWaitEvent(0, Ev[9], 0);
    cudaStreamWaitEvent(0, Ev[11], 0);
}

// round 16
// speedup vs baseline: 1.0497x; 1.0142x over previous
#include <cuda_runtime.h>
#include <math.h>

#define NMmax 100000
#define NPmax 10000
#define NEmax 1000000
#define Hc  128
#define EDc 8

typedef unsigned long long ull;

__device__ float g_hmA[NMmax*Hc];
__device__ float g_hmB[NMmax*Hc];
__device__ float g_hpA[NPmax*Hc];
__device__ float g_hpB[NPmax*Hc];
__device__ float g_xs1[NMmax*Hc];
__device__ float g_xs2[NMmax*Hc];
__device__ float g_hidm[NMmax*Hc];
__device__ float g_hidp[NPmax*Hc];
__device__ float g_P[NPmax*Hc];
__device__ float g_alpham[NEmax];
__device__ float g_alphap[NEmax];
__device__ float g_ssrc1[NMmax];
__device__ float g_ssrc2[NMmax];
__device__ float g_sdstm[NMmax];
__device__ float g_sdstp[NPmax];
__device__ float g_effdstA[4*Hc];
__device__ float g_effedgeA[4*EDc];
__device__ int   g_cntm[NMmax];
__device__ int   g_curm[NMmax];
__device__ int   g_cntp[NPmax];
__device__ int   g_curp[NPmax];
__device__ int   g_offm[NMmax+1];
__device__ int   g_offp[NPmax+1];
__device__ int   g_srcm[NEmax];
__device__ int   g_srcp[NEmax];
__device__ float g_eam[NEmax*EDc];
__device__ float g_eap[NEmax*EDc];
__device__ int   g_bsumM[128];
__device__ int   g_bpreM[128];
__device__ int   g_bsumP[128];
__device__ int   g_bpreP[128];

__device__ __forceinline__ ull ffma2(ull a, ull b, ull c){
    ull d;
    asm("fma.rn.f32x2 %0, %1, %2, %3;" : "=l"(d) : "l"(a), "l"(b), "l"(c));
    return d;
}
__device__ __forceinline__ ull bcast2(float x){
    ull d;
    asm("mov.b64 %0, {%1, %1};" : "=l"(d) : "f"(x));
    return d;
}
__device__ __forceinline__ void unpack2(ull v, float& lo, float& hi){
    asm("mov.b64 {%0, %1}, %2;" : "=f"(lo), "=f"(hi) : "l"(v));
}

__global__ void zero2(int* __restrict__ a, int* __restrict__ b, int n){
    int i = blockIdx.x*256 + threadIdx.x;
    if(i<n){ a[i]=0; b[i]=0; }
}
__global__ void hist_kernel(const int* __restrict__ idx, int* __restrict__ cnt, int n){
    int e = blockIdx.x*256 + threadIdx.x;
    if(e<n) atomicAdd(&cnt[idx[e]], 1);
}
__global__ void scan_blk(const int* __restrict__ cnt, int* __restrict__ off,
                         int* __restrict__ bsum, int n){
    __shared__ int wsum[32];
    int base = blockIdx.x*1024;
    int t = threadIdx.x, lane=t&31, w=t>>5;
    int v = (base+t<n)?cnt[base+t]:0;
    int s=v;
    #pragma unroll
    for(int o=1;o<32;o<<=1){ int x=__shfl_up_sync(0xffffffffu,s,o); if(lane>=o) s+=x; }
    if(lane==31) wsum[w]=s;
    __syncthreads();
    if(w==0){
        int ws=wsum[lane];
        #pragma unroll
        for(int o=1;o<32;o<<=1){ int x=__shfl_up_sync(0xffffffffu,ws,o); if(lane>=o) ws+=x; }
        wsum[lane]=ws;
    }
    __syncthreads();
    int incl = s + (w>0?wsum[w-1]:0);
    if(base+t<n) off[base+t+1] = incl;
    if(t==1023) bsum[blockIdx.x] = incl;
}
__global__ void scan_top(int* __restrict__ off, const int* __restrict__ bsum,
                         int* __restrict__ bpre, int nblk){
    __shared__ int wsum[4];
    int t=threadIdx.x, lane=t&31, w=t>>5;
    int v = (t<nblk)? bsum[t]:0;
    int s=v;
    #pragma unroll
    for(int o=1;o<32;o<<=1){ int x=__shfl_up_sync(0xffffffffu,s,o); if(lane>=o) s+=x; }
    if(lane==31) wsum[w]=s;
    __syncthreads();
    int add=0;
    #pragma unroll
    for(int ww=0;ww<4;ww++) if(ww<w) add += wsum[ww];
    bpre[t] = s + add - v;
    if(t==0) off[0]=0;
}
__global__ void scan_add(int* __restrict__ off, const int* __restrict__ bpre, int n){
    int i = blockIdx.x*256 + threadIdx.x;
    if(i<n) off[i+1] += bpre[i>>10];
}
__global__ void scatter_perm(const int* __restrict__ idx, const int* __restrict__ other,
                             const float* __restrict__ eattr,
                             const int* __restrict__ off, int* __restrict__ cur,
                             int* __restrict__ srcout, float* __restrict__ eaout, int n){
    int e = blockIdx.x*256 + threadIdx.x;
    if(e<n){
        int d = idx[e];
        int p = atomicAdd(&cur[d], 1);
        int pos = off[d]+p;
        srcout[pos] = other[e];
        float4 u = __ldg((const float4*)(eattr + (size_t)e*EDc));
        float4 w = __ldg((const float4*)(eattr + (size_t)e*EDc + 4));
        *(float4*)(eaout + (size_t)pos*EDc)     = u;
        *(float4*)(eaout + (size_t)pos*EDc + 4) = w;
    }
}
// parallel-reduced eff: 8 threads per output column, 3 butterfly shuffles
__global__ void eff_all(const float* __restrict__ Wdst, const float* __restrict__ We,
                        const float* __restrict__ adst, const float* __restrict__ aedge){
    int c = blockIdx.x;
    int tid = threadIdx.x;           // 1024
    const float* Wd = Wdst + (size_t)c*Hc*Hc;
    const float* ad = adst + c*Hc;
    int t = tid >> 3, g = tid & 7;
    float s = 0.f;
    int j0 = g*16;
    #pragma unroll
    for(int j=0;j<16;j++) s = fmaf(Wd[(j0+j)*Hc + t], ad[j0+j], s);
    s += __shfl_xor_sync(0xffffffffu, s, 1);
    s += __shfl_xor_sync(0xffffffffu, s, 2);
    s += __shfl_xor_sync(0xffffffffu, s, 4);
    if(g==0) g_effdstA[c*Hc + t] = s;
    if(tid < 64){                    // warps 0-1 entirely: full-warp convergence
        const float* W = We + (size_t)c*Hc*EDc;
        const float* ae = aedge + c*Hc;
        int ch = tid >> 3;
        float e = 0.f;
        #pragma unroll
        for(int j=0;j<16;j++) e = fmaf(W[(j0+j)*EDc + ch], ae[j0+j], e);
        e += __shfl_xor_sync(0xffffffffu, e, 1);
        e += __shfl_xor_sync(0xffffffffu, e, 2);
        e += __shfl_xor_sync(0xffffffffu, e, 4);
        if(g==0) g_effedgeA[c*EDc + ch] = e;
    }
}

// ---------------- GEMM (champion: no prefetch, BM=128, 2 blocks/SM) ----------------
template<int N, int K, int LDW, int ACT>
__global__ void __launch_bounds__(256) gemm_kernel(const float* __restrict__ A,
                                                   const float* __restrict__ W,
                                                   const float* __restrict__ bias,
                                                   float* __restrict__ C, int M,
                                                   const float* __restrict__ dotvec,
                                                   float* __restrict__ dotout){
    constexpr int BM = 128;
    constexpr int KC = 32;
    constexpr int TN = N/32;
    constexpr int WS = N + 4;
    constexpr int ASD = BM + 2;
    __shared__ float As[KC*ASD];
    __shared__ float Ws[KC*WS];
    int tid  = threadIdx.x;
    int warp = tid>>5, lane = tid&31;
    int r0 = warp*16;
    int c0 = lane*TN;
    int row0 = blockIdx.x*BM;
    ull acc2[8][TN];
    #pragma unroll
    for(int i=0;i<8;i++)
        #pragma unroll
        for(int j=0;j<TN;j++) acc2[i][j]=0ull;

    for(int ko=0; ko<K; ko+=KC){
        #pragma unroll
        for(int l=0; l<(BM*KC)/(256*4); l++){
            int idx = tid + l*256;
            int r = idx>>3, kq = idx&7;
            float4 v = make_float4(0,0,0,0);
            int grow = row0 + r;
            if(grow < M) v = *(const float4*)(A + (size_t)grow*K + ko + kq*4);
            As[(kq*4+0)*ASD + r] = v.x;
            As[(kq*4+1)*ASD + r] = v.y;
            As[(kq*4+2)*ASD + r] = v.z;
            As[(kq*4+3)*ASD + r] = v.w;
        }
        for(int idx=tid; idx<KC*N; idx+=256){
            int kk = idx & (KC-1), n = idx/KC;
            Ws[kk*WS + n] = W[(size_t)n*LDW + ko + kk];
        }
        __syncthreads();
        #pragma unroll 4
        for(int k=0;k<KC;k++){
            ull a2[8];
            #pragma unroll
            for(int i=0;i<8;i++) a2[i] = *(const ull*)(As + k*ASD + r0 + 2*i);
            ull wb[TN];
            if constexpr(TN==4){
                float4 w4 = *(const float4*)(Ws + k*WS + c0);
                wb[0]=bcast2(w4.x); wb[1]=bcast2(w4.y); wb[2]=bcast2(w4.z); wb[3]=bcast2(w4.w);
            } else {
                float2 w2 = *(const float2*)(Ws + k*WS + c0);
                wb[0]=bcast2(w2.x); wb[1]=bcast2(w2.y);
            }
            #pragma unroll
            for(int i=0;i<8;i++)
                #pragma unroll
                for(int j=0;j<TN;j++) acc2[i][j] = ffma2(a2[i], wb[j], acc2[i][j]);
        }
        __syncthreads();
    }
    float dv[TN];
    float dr[16];
    if(dotvec){
        #pragma unroll
        for(int j=0;j<TN;j++) dv[j] = dotvec[c0+j];
        #pragma unroll
        for(int r=0;r<16;r++) dr[r]=0.f;
    }
    #pragma unroll
    for(int i=0;i<8;i++){
        int gr0 = row0 + r0 + 2*i;
        #pragma unroll
        for(int j=0;j<TN;j++){
            float lo, hi;
            unpack2(acc2[i][j], lo, hi);
            float bv = bias ? bias[c0+j] : 0.f;
            lo += bv; hi += bv;
            if(ACT==1){ lo = fmaxf(lo,0.f); hi = fmaxf(hi,0.f); }
            if(ACT==2){ lo = lo>0.f?lo:(__expf(lo)-1.f); hi = hi>0.f?hi:(__expf(hi)-1.f); }
            if(gr0   < M) C[(size_t)gr0    *N + c0 + j] = lo;
            if(gr0+1 < M) C[(size_t)(gr0+1)*N + c0 + j] = hi;
            if(dotvec){
                dr[2*i]   = fmaf(lo, dv[j], dr[2*i]);
                dr[2*i+1] = fmaf(hi, dv[j], dr[2*i+1]);
            }
        }
    }
    if(dotvec){
        #pragma unroll
        for(int r=0;r<16;r++){
            float s = dr[r];
            #pragma unroll
            for(int o=16;o;o>>=1) s += __shfl_xor_sync(0xffffffffu, s, o);
            int grow = row0 + r0 + r;
            if(lane==0 && grow < M) dotout[grow] = s;
        }
    }
}

// ---------------- champion conv: two-pass, logits+amax, 4-edge unroll ----------------
__global__ void __launch_bounds__(256) conv_main(
    const float* __restrict__ xs, const float* __restrict__ xdst,
    const float* __restrict__ ssrc, const float* __restrict__ sdst,
    const int* __restrict__ off, const int* __restrict__ srcarr,
    const float* __restrict__ eattrp, float* __restrict__ alpha,
    const float* __restrict__ We, const float* __restrict__ effedge,
    float* __restrict__ hout, int Nd,
    const float* __restrict__ next_effdst, float* __restrict__ next_sdst)
{
    int warp = threadIdx.x>>5, lane = threadIdx.x&31;
    int d = blockIdx.x*8 + warp;
    if(d >= Nd) return;

    float ae[8];
    #pragma unroll
    for(int c=0;c<8;c++) ae[c] = __ldg(effedge + c);

    int beg = off[d];
    int deg = off[d+1] - beg;
    float sd = sdst[d];

    float amax = -3.0e38f;
    for(int i=lane; i<deg; i+=32){
        int s = __ldg(srcarr + beg+i);
        float a = __ldg(ssrc + s) + sd;
        float4 u = __ldg((const float4*)(eattrp + (size_t)(beg+i)*EDc));
        float4 w = __ldg((const float4*)(eattrp + (size_t)(beg+i)*EDc + 4));
        a = fmaf(u.x,ae[0], fmaf(u.y,ae[1], fmaf(u.z,ae[2], fmaf(u.w,ae[3], a))));
        a = fmaf(w.x,ae[4], fmaf(w.y,ae[5], fmaf(w.z,ae[6], fmaf(w.w,ae[7], a))));
        a = a>0.f ? a : 0.01f*a;
        alpha[beg+i] = a;
        amax = fmaxf(amax, a);
    }
    #pragma unroll
    for(int o=16;o;o>>=1) amax = fmaxf(amax, __shfl_xor_sync(0xffffffffu, amax, o));
    __syncwarp();

    float acc[4] = {0.f,0.f,0.f,0.f};
    float den = 0.f;
    float eaacc = 0.f;
    int q = lane>>3, c8 = lane&7;
    int i = 0;
    for(; i+4<=deg; i+=4){
        int b = beg+i;
        float ex0=__expf(alpha[b+0]-amax);
        float ex1=__expf(alpha[b+1]-amax);
        float ex2=__expf(alpha[b+2]-amax);
        float ex3=__expf(alpha[b+3]-amax);
        int s0=__ldg(srcarr+b+0), s1=__ldg(srcarr+b+1), s2=__ldg(srcarr+b+2), s3=__ldg(srcarr+b+3);
        float4 x0=__ldg((const float4*)(xs+(size_t)s0*Hc+lane*4));
        float4 x1=__ldg((const float4*)(xs+(size_t)s1*Hc+lane*4));
        float4 x2=__ldg((const float4*)(xs+(size_t)s2*Hc+lane*4));
        float4 x3=__ldg((const float4*)(xs+(size_t)s3*Hc+lane*4));
        float exq = (q==0)?ex0:(q==1)?ex1:(q==2)?ex2:ex3;
        float ev = __ldg(eattrp + (size_t)(b+q)*EDc + c8);
        eaacc = fmaf(exq, ev, eaacc);
        den += ex0+ex1+ex2+ex3;
        acc[0]=fmaf(ex0,x0.x,acc[0]); acc[1]=fmaf(ex0,x0.y,acc[1]); acc[2]=fmaf(ex0,x0.z,acc[2]); acc[3]=fmaf(ex0,x0.w,acc[3]);
        acc[0]=fmaf(ex1,x1.x,acc[0]); acc[1]=fmaf(ex1,x1.y,acc[1]); acc[2]=fmaf(ex1,x1.z,acc[2]); acc[3]=fmaf(ex1,x1.w,acc[3]);
        acc[0]=fmaf(ex2,x2.x,acc[0]); acc[1]=fmaf(ex2,x2.y,acc[1]); acc[2]=fmaf(ex2,x2.z,acc[2]); acc[3]=fmaf(ex2,x2.w,acc[3]);
        acc[0]=fmaf(ex3,x3.x,acc[0]); acc[1]=fmaf(ex3,x3.y,acc[1]); acc[2]=fmaf(ex3,x3.z,acc[2]); acc[3]=fmaf(ex3,x3.w,acc[3]);
    }
    for(; i<deg; i++){
        int b = beg+i;
        float ex = __expf(alpha[b]-amax);
        den += ex;
        int s = __ldg(srcarr+b);
        float4 xv = __ldg((const float4*)(xs+(size_t)s*Hc+lane*4));
        acc[0]=fmaf(ex,xv.x,acc[0]); acc[1]=fmaf(ex,xv.y,acc[1]); acc[2]=fmaf(ex,xv.z,acc[2]); acc[3]=fmaf(ex,xv.w,acc[3]);
        if(lane < EDc) eaacc = fmaf(ex, __ldg(eattrp + (size_t)b*EDc + lane), eaacc);
    }
    eaacc += __shfl_xor_sync(0xffffffffu, eaacc, 8);
    eaacc += __shfl_xor_sync(0xffffffffu, eaacc, 16);
    float eac[8];
    #pragma unroll
    for(int c=0;c<8;c++) eac[c] = __shfl_sync(0xffffffffu, eaacc, c);

    float inv = den>0.f ? 1.f/den : 0.f;
    float4 xd = __ldg((const float4*)(xdst + (size_t)d*Hc + lane*4));
    float xda[4] = {xd.x, xd.y, xd.z, xd.w};
    float vv[4];
    float dotp = 0.f;
    #pragma unroll
    for(int j=0;j<4;j++){
        int ch = lane*4 + j;
        float4 wa = __ldg((const float4*)(We + ch*EDc));
        float4 wb = __ldg((const float4*)(We + ch*EDc + 4));
        float ep = eac[0]*wa.x + eac[1]*wa.y + eac[2]*wa.z + eac[3]*wa.w
                 + eac[4]*wb.x + eac[5]*wb.y + eac[6]*wb.z + eac[7]*wb.w;
        float v = (acc[j] + ep)*inv + xda[j];
        v = v>0.f ? v : (__expf(v)-1.f);
        vv[j] = v;
        if(next_effdst) dotp = fmaf(v, __ldg(next_effdst + ch), dotp);
    }
    *(float4*)(hout + (size_t)d*Hc + lane*4) = make_float4(vv[0],vv[1],vv[2],vv[3]);
    if(next_effdst){
        #pragma unroll
        for(int o=16;o;o>>=1) dotp += __shfl_xor_sync(0xffffffffu, dotp, o);
        if(lane==0) next_sdst[d] = dotp;
    }
}

// 16 lanes per edge, 2 edges per warp
__global__ void __launch_bounds__(256) edge_out_kernel(
    const float* __restrict__ P, const float* __restrict__ Mt,
    const int* __restrict__ eprov, const int* __restrict__ emem,
    const float* __restrict__ W2, const float* __restrict__ b2,
    float* __restrict__ out, int E)
{
    int lane = threadIdx.x & 31;
    int l16 = lane & 15, g = lane >> 4;
    int wg = (blockIdx.x*256 + threadIdx.x) >> 5;
    int nw = (gridDim.x*256) >> 5;
    float4 w2a[8], w2b[8];
    #pragma unroll
    for(int c=0;c<8;c++){
        w2a[c] = *(const float4*)(W2 + c*128 + l16*8);
        w2b[c] = *(const float4*)(W2 + c*128 + l16*8 + 4);
    }
    float bb[8];
    #pragma unroll
    for(int c=0;c<8;c++) bb[c] = b2[c];

    for(int e0=wg*2; e0<E; e0+=nw*2){
        int e = e0 + g;
        bool valid = e < E;
        int p = valid ? __ldg(eprov+e) : 0;
        int m = valid ? __ldg(emem+e)  : 0;
        float4 pa = *(const float4*)(P  + (size_t)p*128 + l16*8);
        float4 pb = *(const float4*)(P  + (size_t)p*128 + l16*8 + 4);
        float4 ma = *(const float4*)(Mt + (size_t)m*128 + l16*8);
        float4 mb = *(const float4*)(Mt + (size_t)m*128 + l16*8 + 4);
        float4 ha, hb;
        ha.x = fmaxf(pa.x+ma.x, 0.f); ha.y = fmaxf(pa.y+ma.y, 0.f);
        ha.z = fmaxf(pa.z+ma.z, 0.f); ha.w = fmaxf(pa.w+ma.w, 0.f);
        hb.x = fmaxf(pb.x+mb.x, 0.f); hb.y = fmaxf(pb.y+mb.y, 0.f);
        hb.z = fmaxf(pb.z+mb.z, 0.f); hb.w = fmaxf(pb.w+mb.w, 0.f);
        float s[8];
        #pragma unroll
        for(int c=0;c<8;c++){
            float4 wa = w2a[c], wb = w2b[c];
            float t = fmaf(ha.x,wa.x, fmaf(ha.y,wa.y, fmaf(ha.z,wa.z, ha.w*wa.w)));
            s[c] = fmaf(hb.x,wb.x, fmaf(hb.y,wb.y, fmaf(hb.z,wb.z, fmaf(hb.w,wb.w, t))));
        }
        #pragma unroll
        for(int o=8;o;o>>=1){
            #pragma unroll
            for(int c=0;c<8;c++) s[c] += __shfl_xor_sync(0xffffffffu, s[c], o);
        }
        if(l16==0 && valid){
            float4 o1 = make_float4(s[0]+bb[0], s[1]+bb[1], s[2]+bb[2], s[3]+bb[3]);
            float4 o2 = make_float4(s[4]+bb[4], s[5]+bb[5], s[6]+bb[6], s[7]+bb[7]);
            *(float4*)(out + (size_t)e*8)     = o1;
            *(float4*)(out + (size_t)e*8 + 4) = o2;
        }
    }
}

static inline void* sym(const void* s){ void* p=nullptr; cudaGetSymbolAddress(&p, s); return p; }

extern "C" void kernel_launch(void* const* d_in, const int* in_sizes, int n_in,
                              void* d_out, int out_size) {
    const float* x_member   = (const float*)d_in[0];
    const float* x_provider = (const float*)d_in[1];
    const int*   edge_prov  = (const int*)d_in[2];
    const int*   edge_mem   = (const int*)d_in[3];
    const float* edge_attr  = (const float*)d_in[4];
    const float* proj_m_W   = (const float*)d_in[5];
    const float* proj_m_b   = (const float*)d_in[6];
    const float* proj_p_W   = (const float*)d_in[7];
    const float* proj_p_b   = (const float*)d_in[8];
    const float* conv_Wsrc  = (const float*)d_in[9];
    const float* conv_Wdst  = (const float*)d_in[10];
    const float* conv_We    = (const float*)d_in[11];
    const float* conv_asrc  = (const float*)d_in[12];
    const float* conv_adst  = (const float*)d_in[13];
    const float* conv_aedge = (const float*)d_in[14];
    const float* final_m_W  = (const float*)d_in[15];
    const float* final_m_b  = (const float*)d_in[16];
    const float* final_p_W  = (const float*)d_in[17];
    const float* final_p_b  = (const float*)d_in[18];
    const float* dec_m_W1   = (const float*)d_in[19];
    const float* dec_m_b1   = (const float*)d_in[20];
    const float* dec_m_W2   = (const float*)d_in[21];
    const float* dec_m_b2   = (const float*)d_in[22];
    const float* dec_p_W1   = (const float*)d_in[23];
    const float* dec_p_b1   = (const float*)d_in[24];
    const float* dec_p_W2   = (const float*)d_in[25];
    const float* dec_p_b2   = (const float*)d_in[26];
    const float* dec_e_W1   = (const float*)d_in[27];
    const float* dec_e_b1   = (const float*)d_in[28];
    const float* dec_e_W2   = (const float*)d_in[29];
    const float* dec_e_b2   = (const float*)d_in[30];

    const int NM = in_sizes[0] / 128;
    const int NP = in_sizes[1] / 64;
    const int E  = in_sizes[2];

    float* out = (float*)d_out;
    float* o_xhm = out;
    float* o_xhp = o_xhm + (size_t)NM*128;
    float* o_zm  = o_xhp + (size_t)NP*64;
    float* o_zp  = o_zm  + (size_t)NM*64;
    float* o_eh  = o_zp  + (size_t)NP*64;

    float* hmA = (float*)sym(g_hmA); float* hmB = (float*)sym(g_hmB);
    float* hpA = (float*)sym(g_hpA); float* hpB = (float*)sym(g_hpB);
    float* xs1 = (float*)sym(g_xs1); float* xs2 = (float*)sym(g_xs2);
    float* hidm = (float*)sym(g_hidm); float* hidp = (float*)sym(g_hidp);
    float* Ptab = (float*)sym(g_P);
    float* alm = (float*)sym(g_alpham); float* alp = (float*)sym(g_alphap);
    float* ssrc1 = (float*)sym(g_ssrc1); float* ssrc2 = (float*)sym(g_ssrc2);
    float* sdstm = (float*)sym(g_sdstm); float* sdstp = (float*)sym(g_sdstp);
    float* effdstA = (float*)sym(g_effdstA);
    float* effedgeA = (float*)sym(g_effedgeA);
    int* cntm = (int*)sym(g_cntm); int* curm = (int*)sym(g_curm);
    int* cntp = (int*)sym(g_cntp); int* curp = (int*)sym(g_curp);
    int* offm = (int*)sym(g_offm); int* offp = (int*)sym(g_offp);
    int* srcm = (int*)sym(g_srcm); int* srcp = (int*)sym(g_srcp);
    float* eam = (float*)sym(g_eam); float* eap = (float*)sym(g_eap);
    int* bsumM = (int*)sym(g_bsumM); int* bpreM = (int*)sym(g_bpreM);
    int* bsumP = (int*)sym(g_bsumP); int* bpreP = (int*)sym(g_bpreP);

    int gE = (E+255)/256;
    int nbm = (NM+1023)/1024, nbp = (NP+1023)/1024;

    static cudaStream_t s1 = nullptr, s2 = nullptr;
    static cudaEvent_t Ev[12];
    if(!s1){
        cudaStreamCreateWithFlags(&s1, cudaStreamNonBlocking);
        cudaStreamCreateWithFlags(&s2, cudaStreamNonBlocking);
        for(int i=0;i<12;i++) cudaEventCreateWithFlags(&Ev[i], cudaEventDisableTiming);
    }

    // fork
    cudaEventRecord(Ev[0], 0);
    cudaStreamWaitEvent(s1, Ev[0], 0);
    cudaStreamWaitEvent(s2, Ev[0], 0);

    eff_all<<<4,1024>>>(conv_Wdst, conv_We, conv_adst, conv_aedge);
    cudaEventRecord(Ev[1], 0);
    zero2<<<(NM+255)/256,256,0,s1>>>(cntm, curm, NM);
    zero2<<<(NP+255)/256,256,0,s2>>>(cntp, curp, NP);
    // flagship member projection
    gemm_kernel<128,128,128,2><<<(NM+127)/128,256>>>(x_member, proj_m_W, proj_m_b, hmA, NM,
                                                     effdstA + 0*128, sdstm);
    cudaEventRecord(Ev[2], 0);

    // s1: member CSR
    hist_kernel<<<gE,256,0,s1>>>(edge_mem, cntm, E);
    scan_blk<<<nbm,1024,0,s1>>>(cntm, offm, bsumM, NM);
    scan_top<<<1,128,0,s1>>>(offm, bsumM, bpreM, nbm);
    scan_add<<<(NM+255)/256,256,0,s1>>>(offm, bpreM, NM);
    scatter_perm<<<gE,256,0,s1>>>(edge_mem, edge_prov, edge_attr, offm, curm, srcm, eam, E);
    cudaEventRecord(Ev[3], s1);

    // s2: provider CSR + proj_p
    hist_kernel<<<gE,256,0,s2>>>(edge_prov, cntp, E);
    scan_blk<<<nbp,1024,0,s2>>>(cntp, offp, bsumP, NP);
    scan_top<<<1,128,0,s2>>>(offp, bsumP, bpreP, nbp);
    scan_add<<<(NP+255)/256,256,0,s2>>>(offp, bpreP, NP);
    scatter_perm<<<gE,256,0,s2>>>(edge_prov, edge_mem, edge_attr, offp, curp, srcp, eap, E);
    cudaStreamWaitEvent(s2, Ev[1], 0);
    gemm_kernel<128,64,64,2><<<(NP+127)/128,256,0,s2>>>(x_provider, proj_p_W, proj_p_b, hpA, NP,
                                                        effdstA + 1*128, sdstp);
    cudaEventRecord(Ev[4], s2);

    // layer 0
    cudaStreamWaitEvent(0, Ev[4], 0);
    gemm_kernel<128,128,128,0><<<(NP+127)/128,256>>>(hpA, conv_Wsrc + (size_t)0*128*128, nullptr, xs1, NP,
                                                     conv_asrc + 0*128, ssrc1);
    cudaStreamWaitEvent(0, Ev[3], 0);
    conv_main<<<(NM+7)/8,256>>>(xs1, hmA, ssrc1, sdstm, offm, srcm, eam, alm,
                                conv_We + (size_t)0*128*8, effedgeA + 0*8, hmB, NM,
                                effdstA + 2*128, sdstm);
    cudaEventRecord(Ev[5], 0);
    cudaStreamWaitEvent(s1, Ev[2], 0);
    gemm_kernel<128,128,128,0><<<(NM+127)/128,256,0,s1>>>(hmA, conv_Wsrc + (size_t)1*128*128, nullptr, xs2, NM,
                                                          conv_asrc + 1*128, ssrc2);
    cudaStreamWaitEvent(s1, Ev[4], 0);
    conv_main<<<(NP+7)/8,256,0,s1>>>(xs2, hpA, ssrc2, sdstp, offp, srcp, eap, alp,
                                     conv_We + (size_t)1*128*8, effedgeA + 1*8, hpB, NP,
                                     effdstA + 3*128, sdstp);
    cudaEventRecord(Ev[6], s1);

    // layer 1
    cudaStreamWaitEvent(0, Ev[6], 0);
    gemm_kernel<128,128,128,0><<<(NP+127)/128,256>>>(hpB, conv_Wsrc + (size_t)2*128*128, nullptr, xs1, NP,
                                                     conv_asrc + 2*128, ssrc1);
    conv_main<<<(NM+7)/8,256>>>(xs1, hmB, ssrc1, sdstm, offm, srcm, eam, alm,
                                conv_We + (size_t)2*128*8, effedgeA + 2*8, hmA, NM,
                                nullptr, nullptr);
    cudaStreamWaitEvent(s1, Ev[5], 0);
    gemm_kernel<128,128,128,0><<<(NM+127)/128,256,0,s1>>>(hmB, conv_Wsrc + (size_t)3*128*128, nullptr, xs2, NM,
                                                          conv_asrc + 3*128, ssrc2);
    conv_main<<<(NP+7)/8,256,0,s1>>>(xs2, hpB, ssrc2, sdstp, offp, srcp, eap, alp,
                                     conv_We + (size_t)3*128*8, effedgeA + 3*8, hpA, NP,
                                     nullptr, nullptr);

    // member decoder head on d: zm, fork Mtab to s2
    gemm_kernel<64,128,128,0><<<(NM+127)/128,256>>>(hmA, final_m_W, final_m_b, o_zm, NM, nullptr, nullptr);
    cudaEventRecord(Ev[7], 0);                    // zm ready
    cudaStreamWaitEvent(s2, Ev[7], 0);
    gemm_kernel<128,64,128,0><<<(NM+127)/128,256,0,s2>>>(o_zm, dec_e_W1 + 64, nullptr, xs1, NM, nullptr, nullptr);
    cudaEventRecord(Ev[8], s2);                   // Mtab ready
    gemm_kernel<128,64,64,1>  <<<(NM+127)/128,256>>>(o_zm, dec_m_W1, dec_m_b1, hidm, NM, nullptr, nullptr);

    // s1: zp -> Ptab -> edge_out
    gemm_kernel<64,128,128,0><<<(NP+127)/128,256,0,s1>>>(hpA, final_p_W, final_p_b, o_zp, NP, nullptr, nullptr);
    cudaEventRecord(Ev[10], s1);                  // zp ready
    gemm_kernel<128,64,128,0><<<(NP+127)/128,256,0,s1>>>(o_zp, dec_e_W1, dec_e_b1, Ptab, NP, nullptr, nullptr);
    cudaStreamWaitEvent(s1, Ev[8], 0);
    edge_out_kernel<<<2048,256,0,s1>>>(Ptab, xs1, edge_prov, edge_mem,
                                       dec_e_W2, dec_e_b2, o_eh, E);
    cudaEventRecord(Ev[9], s1);

    // s2: provider reconstruction after Mtab (needs zp)
    cudaStreamWaitEvent(s2, Ev[10], 0);
    gemm_kernel<128,64,64,1><<<(NP+127)/128,256,0,s2>>>(o_zp, dec_p_W1, dec_p_b1, hidp, NP, nullptr, nullptr);
    gemm_kernel<64,128,128,0><<<(NP+127)/128,256,0,s2>>>(hidp, dec_p_W2, dec_p_b2, o_xhp, NP, nullptr, nullptr);
    cudaEventRecord(Ev[11], s2);

    // d: member reconstruction (overlaps edge_out), then join all
    gemm_kernel<128,128,128,0><<<(NM+127)/128,256>>>(hidm, dec_m_W2, dec_m_b2, o_xhm, NM, nullptr, nullptr);
    cudaStreamWaitEvent(0, Ev[9], 0);
    cudaStreamWaitEvent(0, Ev[11], 0);
}